// round 7
// baseline (speedup 1.0000x reference)
#include <cuda_runtime.h>

// AnalyticalBoundedLineAttractor — analytic piecewise-affine ODE integrator.
//
// Per step: z = Wx + b; m = (z>0); x' = x + p1 + p2 with
//   p1 = DT*(relu(z) - x),  p2 = (m .* (W'p1) - DT*p1)/2,  W' = DT*W.
// Identity used: W'p1 = W'relu(z) - DT*(W'x), and (W'x)_r = dwx_r is already
// in-lane from dot 1 — so dot 2 runs on relu(z), ready 1 FMNMX after dot 1.
// K = 2 Taylor terms (measured rel_err 4.6e-4 vs 1e-3 gate).
//
// Round-7 structure: ONE WARP PER ELEMENT, zero smem, zero barriers.
// Lane j owns rows j and j+32; state pair (x_j, x_j+32) lives in one u64.
// Matvec = 31 independent 64-bit butterfly shuffles of the pair + 64
// fma.rn.f32x2 against a butterfly-pre-rotated W register layout:
//   wA[k] = (W'[j][j^k], W'[j][(j^k)+32]),  wB[k] = same for row j+32.
// (x^k for k=0..31 visits every lane; static wA[k] indexing via full unroll.)
// This deletes the per-dot named-barrier (~47cyc) + LDS (29cyc) + STS
// exchange that dominated rounds 3-6.
//
// Geometry: 4 elements per 128-thread CTA, grid=64 -> one CTA/SM, each
// warp on its own SMSP, all 256 latency chains concurrent in one wave.

#define DIMV 64
#define DTC  0.05f

using u64 = unsigned long long;

__device__ __forceinline__ u64 fma2(u64 a, u64 b, u64 c) {
    u64 d; asm("fma.rn.f32x2 %0, %1, %2, %3;" : "=l"(d) : "l"(a), "l"(b), "l"(c));
    return d;
}
__device__ __forceinline__ u64 add2(u64 a, u64 b) {
    u64 d; asm("add.rn.f32x2 %0, %1, %2;" : "=l"(d) : "l"(a), "l"(b));
    return d;
}
__device__ __forceinline__ u64 pack2(float lo, float hi) {
    u64 d; asm("mov.b64 %0, {%1, %2};" : "=l"(d) : "f"(lo), "f"(hi));
    return d;
}
__device__ __forceinline__ void unpack2(u64 s, float& lo, float& hi) {
    asm("mov.b64 {%0, %1}, %2;" : "=f"(lo), "=f"(hi) : "l"(s));
}

__global__ void __launch_bounds__(128, 1)
attractor_kernel(const float* __restrict__ x0,
                 const float* __restrict__ Wg,
                 const float* __restrict__ bg,
                 float* __restrict__ out,
                 int tsteps)
{
    const int lane = threadIdx.x & 31;
    const int wrp  = threadIdx.x >> 5;             // element within CTA
    const int elem = blockIdx.x * 4 + wrp;

    const int r0 = lane;                           // owned rows
    const int r1 = lane + 32;

    // ---- butterfly-rotated W' = DT*W register tiles ----
    // wA[k]/wB[k] pair columns (lane^k, (lane^k)+32) for rows r0/r1.
    u64 wA[32], wB[32];
#pragma unroll
    for (int k = 0; k < 32; k++) {
        int c = lane ^ k;
        wA[k] = pack2(Wg[r0 * DIMV + c] * DTC, Wg[r0 * DIMV + c + 32] * DTC);
        wB[k] = pack2(Wg[r1 * DIMV + c] * DTC, Wg[r1 * DIMV + c + 32] * DTC);
    }
    const float db0 = DTC * bg[r0];
    const float db1 = DTC * bg[r1];

    float xi0 = x0[(size_t)elem * DIMV + r0];
    float xi1 = x0[(size_t)elem * DIMV + r1];
    float* outp = out + (size_t)elem * tsteps * DIMV;

    // matvec2: y_{r0,r1} = (W' v)_{r0,r1}, v distributed as lane pairs.
    // 31 independent u64 butterfly shuffles + 64 FMA2, 4 accs per row.
    auto matvec2 = [&](u64 v, float& y0, float& y1) {
        u64 aA[4], aB[4];
        aA[0] = fma2(wA[0], v, 0ull);   aB[0] = fma2(wB[0], v, 0ull);
        aA[1] = 0ull; aA[2] = 0ull; aA[3] = 0ull;
        aB[1] = 0ull; aB[2] = 0ull; aB[3] = 0ull;
#pragma unroll
        for (int k = 1; k < 32; k++) {
            u64 s = __shfl_xor_sync(0xffffffffu, v, k);
            aA[k & 3] = fma2(wA[k], s, aA[k & 3]);
            aB[k & 3] = fma2(wB[k], s, aB[k & 3]);
        }
        u64 sA = add2(add2(aA[0], aA[1]), add2(aA[2], aA[3]));
        u64 sB = add2(add2(aB[0], aB[1]), add2(aB[2], aB[3]));
        float l0, h0, l1, h1;
        unpack2(sA, l0, h0);
        unpack2(sB, l1, h1);
        y0 = l0 + h0;
        y1 = l1 + h1;
    };

#pragma unroll 1
    for (int t = 0; t < tsteps; t++) {
        // trajectory stores x BEFORE the update (off critical path)
        outp[t * DIMV + r0] = xi0;
        outp[t * DIMV + r1] = xi1;

        // dot 1: dwx = (W'x)_r
        u64 vx = pack2(xi0, xi1);
        float dwx0, dwx1;
        matvec2(vx, dwx0, dwx1);

        // shortest path to the dot-2 exchange: z -> relu -> pack
        float z0 = dwx0 + db0;
        float z1 = dwx1 + db1;
        float relu0 = fmaxf(z0, 0.f);
        float relu1 = fmaxf(z1, 0.f);
        u64 vr = pack2(relu0, relu1);

        // dot 2 on relu(z); W'p1 = t2 - DT*dwx recovered per-lane
        float t20, t21;
        matvec2(vr, t20, t21);

        // off-path algebra (hides under dot-2's shuffle/FMA stream):
        //   p1 = relu - DT*x
        //   inner = x + p1 - 0.5*DT*p1 - 0.5*m*DT*dwx
        //   x' = inner + 0.5*m*t2
        float p10 = relu0 - DTC * xi0;
        float p11 = relu1 - DTC * xi1;
        float in0 = fmaf(-0.5f * DTC, p10, xi0 + p10);
        float in1 = fmaf(-0.5f * DTC, p11, xi1 + p11);
        bool  m0  = z0 > 0.f;
        bool  m1  = z1 > 0.f;
        in0 -= m0 ? 0.5f * DTC * dwx0 : 0.f;
        in1 -= m1 ? 0.5f * DTC * dwx1 : 0.f;

        xi0 = fmaf(m0 ? t20 : 0.f, 0.5f, in0);
        xi1 = fmaf(m1 ? t21 : 0.f, 0.5f, in1);
    }
}

extern "C" void kernel_launch(void* const* d_in, const int* in_sizes, int n_in,
                              void* d_out, int out_size)
{
    const float* x0 = (const float*)d_in[0];   // (batch, 64)
    const float* W  = (const float*)d_in[1];   // (64, 64)
    const float* b  = (const float*)d_in[2];   // (64,)
    float* out = (float*)d_out;                // (batch, T, 64)

    int batch  = in_sizes[0] / DIMV;           // 256
    int tsteps = out_size / (batch * DIMV);    // 100

    attractor_kernel<<<batch / 4, 128>>>(x0, W, b, out, tsteps);
}

// round 8
// speedup vs baseline: 1.4237x; 1.4237x over previous
#include <cuda_runtime.h>

// AnalyticalBoundedLineAttractor — analytic piecewise-affine ODE integrator.
//
// Per step: z = Wx + b; m = (z>0); x' = x + p1 + p2 with
//   p1 = DT*(relu(z) - x),  p2 = (m .* (W'p1) - DT*p1)/2,  W' = DT*W.
// K = 2 Taylor terms (measured rel_err 4.6e-4 vs 1e-3 gate).
// Z p = m.*(W'p) - DT*p with W' = DT*W held in registers.
//
// Architecture (best measured across rounds 3-7): 2 elements per
// 128-thread CTA, grid=128 (one CTA/SM, 4 warps on 4 distinct SMSPs),
// per-element NAMED 64-thread barriers so the two chains never couple.
// Exchange = STS + bar + LDS.128 broadcast (shuffle variant measured 2x
// worse: 62 SHFLs/dot at MIO rt ~6 = ~370cyc/dot).
//
// Round-8 deltas (target: measured ~110cyc/step overhead Omega):
//  - trajectory stores x BEFORE update -> x_100 never needed: store x0
//    pre-loop, run 99 updates storing new xi at t+1 right after compute
//    (also pulls the STG out of the bar2->LDS critical path).
//  - time loop unrolled x2 (halve branch cost, cross-step scheduling).
//  - dot uses 2 packed accumulators (rt-2/lat-4 exact fit): tree 20->12.
//  - (1-DT)xi / DT*xi precomputed in bar2's shadow.

#define DIMV 64
#define DTC  0.05f

using u64 = unsigned long long;

__device__ __forceinline__ u64 fma2(u64 a, u64 b, u64 c) {
    u64 d; asm("fma.rn.f32x2 %0, %1, %2, %3;" : "=l"(d) : "l"(a), "l"(b), "l"(c));
    return d;
}
__device__ __forceinline__ u64 add2(u64 a, u64 b) {
    u64 d; asm("add.rn.f32x2 %0, %1, %2;" : "=l"(d) : "l"(a), "l"(b));
    return d;
}

__global__ void __launch_bounds__(128, 1)
attractor_kernel(const float* __restrict__ x0,
                 const float* __restrict__ Wg,
                 const float* __restrict__ bg,
                 float* __restrict__ out,
                 int tsteps)
{
    __shared__ __align__(16) float xs[2][DIMV];    // current x per element
    __shared__ __align__(16) float p1s[2][DIMV];   // term-1 vector per element

    const int tid  = threadIdx.x;
    const int el   = tid >> 6;                     // local element 0/1
    const int i    = tid & 63;                     // row index
    const int elem = blockIdx.x * 2 + el;
    const int bar  = el + 1;                       // named barrier id

    // ---- W row i, pre-scaled by DT, as 32 packed f32x2 pairs ----
    u64 w2[32];
    {
        const float* wrow = Wg + i * DIMV;
#pragma unroll
        for (int q = 0; q < 16; q++) {
            float4 t = reinterpret_cast<const float4*>(wrow)[q];
            float s0 = t.x * DTC, s1 = t.y * DTC, s2 = t.z * DTC, s3 = t.w * DTC;
            asm("mov.b64 %0, {%1, %2};" : "=l"(w2[2*q])   : "f"(s0), "f"(s1));
            asm("mov.b64 %0, {%1, %2};" : "=l"(w2[2*q+1]) : "f"(s2), "f"(s3));
        }
    }
    const float db = DTC * bg[i];                  // DT * b_i
    float xi = x0[(size_t)elem * DIMV + i];

    xs[el][i] = xi;
    float* outp = out + (size_t)elem * tsteps * DIMV + i;
    outp[0] = xi;                                  // x_0 stored up front
    asm volatile("bar.sync %0, 64;" :: "r"(bar) : "memory");

    // dot(DT*W_row_i, buf): 16 x LDS.128 + 32 x fma.f32x2, 2 packed accs
    // (rt 2 x 2 accs == lat 4: zero RAW stall, shortest reduce tree)
    auto dot = [&](const float* buf) -> float {
        const ulonglong2* p16 = reinterpret_cast<const ulonglong2*>(buf);
        u64 a0 = 0ull, a1 = 0ull;
#pragma unroll
        for (int q = 0; q < 16; q++) {
            ulonglong2 v = p16[q];
            a0 = fma2(w2[2*q + 0], v.x, a0);
            a1 = fma2(w2[2*q + 1], v.y, a1);
        }
        u64 s = add2(a0, a1);
        float lo, hi;
        asm("mov.b64 {%0, %1}, %2;" : "=f"(lo), "=f"(hi) : "l"(s));
        return lo + hi;
    };

    float c1xi = (1.0f - DTC) * xi;                // (1-DT)*x
    float dxi  = DTC * xi;                         // DT*x

    // 99 updates: x_100 is never stored, so never computed.
#pragma unroll 2
    for (int t = 1; t < tsteps; t++) {
        // term 1: dwx = DT*(Wx); relu (FMNMX) keeps the chain short
        float dwx  = dot(xs[el]);
        float z    = dwx + db;                     // sign(DT*z) == sign(z)
        float relu = fmaxf(z, 0.f);                // m*z
        float p    = relu - dxi;                   // p1 = DT*(relu(z) - x)
        p1s[el][i] = p;
        asm volatile("bar.sync %0, 64;" :: "r"(bar) : "memory");

        // off critical path (overlaps barrier + LDS of dot 2):
        bool  m     = z > 0.f;                     // predicate for term 2
        float sum   = relu + c1xi;                 // x + p1 (reassociated)
        float inner = sum - (0.5f * DTC) * p;      // x + p1 - (DT/2) p1

        // term 2: x' = inner + 0.5 * (m ? W'p1 : 0)
        float t2 = dot(p1s[el]);
        xi = fmaf(m ? t2 : 0.f, 0.5f, inner);      // 8 cyc after t2

        xs[el][i] = xi;                            // xs readers retired at bar above
        outp[t * DIMV] = xi;                       // store AFTER compute: off-chain
        c1xi = (1.0f - DTC) * xi;                  // bar2-shadow precompute
        dxi  = DTC * xi;
        asm volatile("bar.sync %0, 64;" :: "r"(bar) : "memory");
    }
}

extern "C" void kernel_launch(void* const* d_in, const int* in_sizes, int n_in,
                              void* d_out, int out_size)
{
    const float* x0 = (const float*)d_in[0];   // (batch, 64)
    const float* W  = (const float*)d_in[1];   // (64, 64)
    const float* b  = (const float*)d_in[2];   // (64,)
    float* out = (float*)d_out;                // (batch, T, 64)

    int batch  = in_sizes[0] / DIMV;           // 256
    int tsteps = out_size / (batch * DIMV);    // 100

    attractor_kernel<<<batch / 2, 128>>>(x0, W, b, out, tsteps);
}

// round 9
// speedup vs baseline: 1.5313x; 1.0756x over previous
#include <cuda_runtime.h>

// AnalyticalBoundedLineAttractor — analytic piecewise-affine ODE integrator.
//
// Per step: z = Wx + b; m = (z>0); x' = x + p1 + p2 with
//   p1 = DT*(relu(z) - x),  p2 = (m .* (W'p1) - DT*p1)/2,  W' = DT*W.
// K = 2 Taylor terms (measured rel_err 4.6e-4 vs 1e-3 gate).
//
// Architecture = round-6 measured best: 2 elements per 128-thread CTA,
// grid=128 (one CTA/SM, 4 warps on 4 distinct SMSPs), per-element NAMED
// 64-thread barriers (chains never couple), exchange = STS + bar +
// LDS.128 broadcast, dot = 16 x LDS.128 + 32 x fma.rn.f32x2 with FOUR
// packed accumulators (R8 measured: 2 accs = zero RAW slack = regression).
// Time loop stays '#pragma unroll 1' (R8's unroll-2 rescheduled worse).
//
// Round-9 deltas vs R6 (only the two provably-safe R8 pieces):
//  - 99 updates: x_100 is stored-before-update so never needed; x0 stored
//    pre-loop, new xi stored right after compute (off the bar2->LDS chain,
//    pointer-increment addressing, no IMAD on the serial path).

#define DIMV 64
#define DTC  0.05f

using u64 = unsigned long long;

__device__ __forceinline__ u64 fma2(u64 a, u64 b, u64 c) {
    u64 d; asm("fma.rn.f32x2 %0, %1, %2, %3;" : "=l"(d) : "l"(a), "l"(b), "l"(c));
    return d;
}
__device__ __forceinline__ u64 add2(u64 a, u64 b) {
    u64 d; asm("add.rn.f32x2 %0, %1, %2;" : "=l"(d) : "l"(a), "l"(b));
    return d;
}

__global__ void __launch_bounds__(128, 1)
attractor_kernel(const float* __restrict__ x0,
                 const float* __restrict__ Wg,
                 const float* __restrict__ bg,
                 float* __restrict__ out,
                 int tsteps)
{
    __shared__ __align__(16) float xs[2][DIMV];    // current x per element
    __shared__ __align__(16) float p1s[2][DIMV];   // term-1 vector per element

    const int tid  = threadIdx.x;
    const int el   = tid >> 6;                     // local element 0/1
    const int i    = tid & 63;                     // row index
    const int elem = blockIdx.x * 2 + el;
    const int bar  = el + 1;                       // named barrier id

    // ---- W row i, pre-scaled by DT, as 32 packed f32x2 pairs ----
    u64 w2[32];
    {
        const float* wrow = Wg + i * DIMV;
#pragma unroll
        for (int q = 0; q < 16; q++) {
            float4 t = reinterpret_cast<const float4*>(wrow)[q];
            float s0 = t.x * DTC, s1 = t.y * DTC, s2 = t.z * DTC, s3 = t.w * DTC;
            asm("mov.b64 %0, {%1, %2};" : "=l"(w2[2*q])   : "f"(s0), "f"(s1));
            asm("mov.b64 %0, {%1, %2};" : "=l"(w2[2*q+1]) : "f"(s2), "f"(s3));
        }
    }
    const float db = DTC * bg[i];                  // DT * b_i
    float xi = x0[(size_t)elem * DIMV + i];

    xs[el][i] = xi;
    float* outp = out + (size_t)elem * tsteps * DIMV + i;
    *outp = xi;                                    // x_0 stored up front
    asm volatile("bar.sync %0, 64;" :: "r"(bar) : "memory");

    // dot(DT*W_row_i, buf): 16 x LDS.128 + 32 x fma.f32x2, 4 packed accs
    auto dot = [&](const float* buf) -> float {
        const ulonglong2* p16 = reinterpret_cast<const ulonglong2*>(buf);
        u64 a0 = 0ull, a1 = 0ull, a2 = 0ull, a3 = 0ull;
#pragma unroll
        for (int q = 0; q < 16; q += 2) {
            ulonglong2 v0 = p16[q];
            ulonglong2 v1 = p16[q + 1];
            a0 = fma2(w2[2*q + 0], v0.x, a0);
            a1 = fma2(w2[2*q + 1], v0.y, a1);
            a2 = fma2(w2[2*q + 2], v1.x, a2);
            a3 = fma2(w2[2*q + 3], v1.y, a3);
        }
        u64 s = add2(add2(a0, a1), add2(a2, a3));
        float lo, hi;
        asm("mov.b64 {%0, %1}, %2;" : "=f"(lo), "=f"(hi) : "l"(s));
        return lo + hi;
    };

    // 99 updates: x_100 is never stored, so never computed.
#pragma unroll 1
    for (int t = 1; t < tsteps; t++) {
        const float c1xi = (1.0f - DTC) * xi;      // in dot-1 LDS shadow
        const float dxi  = DTC * xi;

        // term 1: dwx = DT*(Wx); relu (FMNMX) keeps the chain short
        float dwx  = dot(xs[el]);
        float z    = dwx + db;                     // sign(DT*z) == sign(z)
        float relu = fmaxf(z, 0.f);                // m*z
        float p    = relu - dxi;                   // p1 = DT*(relu(z) - x)
        p1s[el][i] = p;
        asm volatile("bar.sync %0, 64;" :: "r"(bar) : "memory");

        // off critical path (overlaps barrier + LDS of dot 2):
        bool  m     = z > 0.f;                     // predicate for term 2
        float sum   = relu + c1xi;                 // x + p1 (reassociated)
        float inner = sum - (0.5f * DTC) * p;      // x + p1 - (DT/2) p1

        // term 2: x' = inner + 0.5 * (m ? W'p1 : 0)
        float t2 = dot(p1s[el]);
        xi = fmaf(m ? t2 : 0.f, 0.5f, inner);      // 8 cyc after t2

        xs[el][i] = xi;                            // xs readers retired at bar above
        outp += DIMV;
        *outp = xi;                                // store AFTER compute: off-chain
        asm volatile("bar.sync %0, 64;" :: "r"(bar) : "memory");
    }
}

extern "C" void kernel_launch(void* const* d_in, const int* in_sizes, int n_in,
                              void* d_out, int out_size)
{
    const float* x0 = (const float*)d_in[0];   // (batch, 64)
    const float* W  = (const float*)d_in[1];   // (64, 64)
    const float* b  = (const float*)d_in[2];   // (64,)
    float* out = (float*)d_out;                // (batch, T, 64)

    int batch  = in_sizes[0] / DIMV;           // 256
    int tsteps = out_size / (batch * DIMV);    // 100

    attractor_kernel<<<batch / 2, 128>>>(x0, W, b, out, tsteps);
}